// round 16
// baseline (speedup 1.0000x reference)
#include <cuda_runtime.h>
#include <math.h>

#define N    2708
#define INC  1433
#define OC   128
#define NCH  32
#define RC   85      // ceil(N/NCH)
#define GZ   4       // gemm K-split
#define NW4  677     // N/4 exactly
#define NPAD 2816    // 88*32, uniform warp compaction trip count
#define XTHR 25.0f   // exp cutoff: dropped mass < N*exp(-25) ~ 4e-8

// ---------------- scratch (static device memory) -----------------------------
__device__ __align__(16) float g_Kp[GZ][N * OC];
__device__ __align__(16) float g_K[N * OC];
__device__ float g_k1[N], g_k2[N];
__device__ __align__(16) float g_part1[NCH * N], g_part2[NCH * N];
__device__ __align__(16) float g_s1[N], g_s2[N];
__device__ float g_p[N], g_q[N];

// ---------------- K = X @ W^T, K-split, register-pipelined --------------------
// BM=64, BN=64, BK=16, 256 threads (2 warps/SMSP), 4x4 thread tile.
__global__ void __launch_bounds__(256) gemm_k(const float* __restrict__ X,
                                              const float* __restrict__ W) {
    __shared__ __align__(16) float Xs[16][68];
    __shared__ __align__(16) float Ws[16][68];
    int i0 = blockIdx.y * 64;
    int c0 = blockIdx.x * 64;
    int z  = blockIdx.z;
    int kb = (INC * z) / GZ;
    int ke = (INC * (z + 1)) / GZ;
    int t  = threadIdx.x;
    int tx = t & 15;      // cols 4tx..4tx+3
    int ty = t >> 4;      // rows 4ty..4ty+3 (0..15 -> 64 rows)
    float acc[4][4] = {};
    float xr[4], wr[4];

#pragma unroll
    for (int l = 0; l < 4; l++) {
        int e = t + l * 256;
        int r = e >> 4, kk = e & 15;
        int gi = i0 + r, gk = kb + kk;
        xr[l] = (gi < N && gk < ke) ? X[(size_t)gi * INC + gk] : 0.f;
    }
#pragma unroll
    for (int l = 0; l < 4; l++) {
        int e = t + l * 256;
        int c = e >> 4, kk = e & 15;
        int gk = kb + kk;
        wr[l] = (gk < ke) ? W[(size_t)(c0 + c) * INC + gk] : 0.f;
    }

    for (int kt = kb; kt < ke; kt += 16) {
#pragma unroll
        for (int l = 0; l < 4; l++) { int e = t + l * 256; Xs[e & 15][e >> 4] = xr[l]; }
#pragma unroll
        for (int l = 0; l < 4; l++) { int e = t + l * 256; Ws[e & 15][e >> 4] = wr[l]; }
        __syncthreads();
        int ktn = kt + 16;
        if (ktn < ke) {
#pragma unroll
            for (int l = 0; l < 4; l++) {
                int e = t + l * 256;
                int r = e >> 4, kk = e & 15;
                int gi = i0 + r, gk = ktn + kk;
                xr[l] = (gi < N && gk < ke) ? X[(size_t)gi * INC + gk] : 0.f;
            }
#pragma unroll
            for (int l = 0; l < 4; l++) {
                int e = t + l * 256;
                int c = e >> 4, kk = e & 15;
                int gk = ktn + kk;
                wr[l] = (gk < ke) ? W[(size_t)(c0 + c) * INC + gk] : 0.f;
            }
        }
#pragma unroll
        for (int kk = 0; kk < 16; kk++) {
            float4 a = *(const float4*)&Xs[kk][4 * ty];
            float4 b = *(const float4*)&Ws[kk][4 * tx];
            acc[0][0] += a.x * b.x; acc[0][1] += a.x * b.y; acc[0][2] += a.x * b.z; acc[0][3] += a.x * b.w;
            acc[1][0] += a.y * b.x; acc[1][1] += a.y * b.y; acc[1][2] += a.y * b.z; acc[1][3] += a.y * b.w;
            acc[2][0] += a.z * b.x; acc[2][1] += a.z * b.y; acc[2][2] += a.z * b.z; acc[2][3] += a.z * b.w;
            acc[3][0] += a.w * b.x; acc[3][1] += a.w * b.y; acc[3][2] += a.w * b.z; acc[3][3] += a.w * b.w;
        }
        __syncthreads();
    }
#pragma unroll
    for (int rr = 0; rr < 4; rr++) {
        int gi = i0 + 4 * ty + rr;
        if (gi < N) {
            float4 v = make_float4(acc[rr][0], acc[rr][1], acc[rr][2], acc[rr][3]);
            *(float4*)&g_Kp[z][(size_t)gi * OC + c0 + 4 * tx] = v;
        }
    }
}

// ---------------- fold GZ partials -> g_K, plus k1,k2 (one warp/row) ---------
__global__ void fold_k1k2(const float* __restrict__ a1, const float* __restrict__ a2) {
    int w = threadIdx.x >> 5;
    int lane = threadIdx.x & 31;
    int i = blockIdx.x * 8 + w;
    if (i >= N) return;
    float d1 = 0.f, d2 = 0.f;
#pragma unroll
    for (int u = 0; u < 4; u++) {
        int c = lane + 32 * u;
        size_t idx = (size_t)i * OC + c;
        float kv = g_Kp[0][idx] + g_Kp[1][idx] + g_Kp[2][idx] + g_Kp[3][idx];
        g_K[idx] = kv;
        d1 += kv * a1[c];
        d2 += kv * a2[c];
    }
#pragma unroll
    for (int off = 16; off; off >>= 1) {
        d1 += __shfl_down_sync(0xffffffffu, d1, off);
        d2 += __shfl_down_sync(0xffffffffu, d2, off);
    }
    if (lane == 0) { g_k1[i] = d1; g_k2[i] = d2; }
}

// ---------------- column partials: t1 = U^T k1, t2 = U^T 1 --------------------
__global__ void colpart(const float* __restrict__ U) {
    int j  = blockIdx.x * 256 + threadIdx.x;
    int ch = blockIdx.y;
    if (j >= N) return;
    int ib = ch * RC;
    int ie = min(N, ib + RC);
    float a = 0.f, b = 0.f;
#pragma unroll 4
    for (int i = ib; i < ie; i++) {
        float u = U[(size_t)i * N + j];
        a += u * g_k1[i];
        b += u;
    }
    g_part1[ch * N + j] = a;
    g_part2[ch * N + j] = b;
}

// ---------------- s = lmbd * t -------------------------------------------------
__global__ void colreduce(const float* __restrict__ lmbd) {
    int j = blockIdx.x * 256 + threadIdx.x;
    if (j >= N) return;
    float a = 0.f, b = 0.f;
#pragma unroll
    for (int c = 0; c < NCH; c++) {
        a += g_part1[c * N + j];
        b += g_part2[c * N + j];
    }
    float l = lmbd[j];
    g_s1[j] = l * a;
    g_s2[j] = l * b;
}

// ---------------- p = U s1, q = U s2 (float4 both sides) -----------------------
__global__ void pq_kernel(const float* __restrict__ U) {
    __shared__ float r1[256], r2[256];
    int i = blockIdx.x;
    int t = threadIdx.x;
    float a = 0.f, b = 0.f;
    const float4* Ur  = (const float4*)(U + (size_t)i * N);
    const float4* s1v = (const float4*)g_s1;
    const float4* s2v = (const float4*)g_s2;
    for (int j4 = t; j4 < NW4; j4 += 256) {
        float4 u  = Ur[j4];
        float4 s1 = s1v[j4];
        float4 s2 = s2v[j4];
        a += u.x * s1.x + u.y * s1.y + u.z * s1.z + u.w * s1.w;
        b += u.x * s2.x + u.y * s2.y + u.z * s2.z + u.w * s2.w;
    }
    r1[t] = a; r2[t] = b;
    __syncthreads();
    for (int s = 128; s; s >>= 1) {
        if (t < s) { r1[t] += r1[t + s]; r2[t] += r2[t + s]; }
        __syncthreads();
    }
    if (t == 0) { g_p[i] = r1[0]; g_q[i] = r2[0]; }
}

// ---------------- sparse masked-softmax attention (single A pass) --------------
// One row per block, 128 threads. Logits cached in smem on the single A read.
// Compaction + weights + denominator done by warp 0 alone (warp-synchronous,
// no block barriers). Weights below exp(-25) of the max dropped consistently
// in numerator and denominator (dropped mass < N*exp(-25) ~ 4e-8).
__global__ void __launch_bounds__(128) attn_sparse(const int* __restrict__ A,
                                                   float* __restrict__ H) {
    __shared__ float sLog[N];      // masked logits (-1e30 if A_ij = 0)
    __shared__ int   sj[N];        // selected j (ascending)
    __shared__ float sw[N];        // selected weights
    __shared__ float red[128];
    __shared__ int   sCnt;
    __shared__ float sInv;

    int i = blockIdx.x;
    int t = threadIdx.x;
    float p = g_p[i];
    float q = g_q[i];
    const int4* Ap = (const int4*)(A + (size_t)i * N);

    // ---- single A pass: masked logits into smem + per-thread max ------------
    float mloc = -1e30f;
#pragma unroll
    for (int l = 0; l < 6; l++) {
        int i4 = t + 128 * l;
        if (i4 < NW4) {
            int4 av = Ap[i4];
            int j = 4 * i4;
            float x0 = av.x ? fabsf(p + q * __ldg(&g_k2[j]))     : -1e30f;
            float x1 = av.y ? fabsf(p + q * __ldg(&g_k2[j + 1])) : -1e30f;
            float x2 = av.z ? fabsf(p + q * __ldg(&g_k2[j + 2])) : -1e30f;
            float x3 = av.w ? fabsf(p + q * __ldg(&g_k2[j + 3])) : -1e30f;
            sLog[j] = x0; sLog[j + 1] = x1; sLog[j + 2] = x2; sLog[j + 3] = x3;
            mloc = fmaxf(fmaxf(x0, x1), fmaxf(fmaxf(x2, x3), mloc));
        }
    }
    red[t] = mloc;
    __syncthreads();
    for (int s = 64; s; s >>= 1) {
        if (t < s) red[t] = fmaxf(red[t], red[t + s]);
        __syncthreads();
    }
    float m = red[0];
    float thr = m - XTHR;

    // ---- warp 0: compaction + weights + denominator (warp-synchronous) ------
    if (t < 32) {
        unsigned lmask = (1u << t) - 1u;
        int cnt = 0;
        float ls = 0.f;
        for (int jb = 0; jb < NPAD; jb += 32) {    // 88 uniform iterations
            int j = jb + t;
            bool pred = (j < N) && (sLog[j] > thr);
            unsigned bal = __ballot_sync(0xffffffffu, pred);
            if (pred) {
                int pos = __popc(bal & lmask);
                float w = __expf(sLog[j] - m);
                sj[cnt + pos] = j;
                sw[cnt + pos] = w;
                ls += w;
            }
            cnt += __popc(bal);
        }
#pragma unroll
        for (int off = 16; off; off >>= 1)
            ls += __shfl_xor_sync(0xffffffffu, ls, off);
        if (t == 0) {
            sCnt = cnt;
            sInv = (ls > 0.f) ? 1.f / ls : 0.f;
        }
    }
    __syncthreads();
    int cnt = sCnt;
    float inv = sInv;

    // ---- numerator: thread t = output column t, gather selected K rows ------
    float a0 = 0.f, a1 = 0.f, a2 = 0.f, a3 = 0.f;
    int e = 0;
    for (; e + 4 <= cnt; e += 4) {
        a0 += sw[e + 0] * __ldg(&g_K[(size_t)sj[e + 0] * OC + t]);
        a1 += sw[e + 1] * __ldg(&g_K[(size_t)sj[e + 1] * OC + t]);
        a2 += sw[e + 2] * __ldg(&g_K[(size_t)sj[e + 2] * OC + t]);
        a3 += sw[e + 3] * __ldg(&g_K[(size_t)sj[e + 3] * OC + t]);
    }
    for (; e < cnt; e++)
        a0 += sw[e] * __ldg(&g_K[(size_t)sj[e] * OC + t]);
    float acc = (a0 + a1) + (a2 + a3);
    H[(size_t)i * OC + t] = acc * inv;
}

// ---------------- launch --------------------------------------------------------
extern "C" void kernel_launch(void* const* d_in, const int* in_sizes, int n_in,
                              void* d_out, int out_size) {
    (void)in_sizes; (void)n_in; (void)out_size;
    const float* X    = (const float*)d_in[0];
    const int*   A    = (const int*)d_in[1];
    const float* U    = (const float*)d_in[2];
    const float* W    = (const float*)d_in[3];
    const float* a1   = (const float*)d_in[4];
    const float* a2   = (const float*)d_in[5];
    const float* lmbd = (const float*)d_in[6];
    float* H = (float*)d_out;

    gemm_k     <<<dim3(2, (N + 63) / 64, GZ), 256>>>(X, W);
    fold_k1k2  <<<(N + 7) / 8, 256>>>(a1, a2);
    colpart    <<<dim3((N + 255) / 256, NCH), 256>>>(U);
    colreduce  <<<(N + 255) / 256, 256>>>(lmbd);
    pq_kernel  <<<N, 256>>>(U);
    attn_sparse<<<N, 128>>>(A, H);
}

// round 17
// speedup vs baseline: 1.0739x; 1.0739x over previous
#include <cuda_runtime.h>
#include <math.h>

#define N    2708
#define INC  1433
#define OC   128
#define NCH  32
#define RC   85      // ceil(N/NCH)
#define GZ   4       // gemm K-split
#define NW4  677     // N/4 exactly
#define NPAD 2816    // 22*128, uniform compaction trip count
#define XTHR 25.0f   // exp cutoff: dropped mass < N*exp(-25) ~ 4e-8

// ---------------- scratch (static device memory) -----------------------------
__device__ __align__(16) float g_Kp[GZ][N * OC];
__device__ __align__(16) float g_K[N * OC];
__device__ float g_k1[N], g_k2[N];
__device__ __align__(16) float g_part1[NCH * N], g_part2[NCH * N];
__device__ __align__(16) float g_s1[N], g_s2[N];
__device__ float g_p[N], g_q[N];

// ---------------- K = X @ W^T, K-split, register-pipelined --------------------
// BM=32, BN=64, BK=16, 128 threads, 4x4 thread tile (R15-proven config).
__global__ void gemm_k(const float* __restrict__ X, const float* __restrict__ W) {
    __shared__ __align__(16) float Xs[16][36];
    __shared__ __align__(16) float Ws[16][68];
    int i0 = blockIdx.y * 32;
    int c0 = blockIdx.x * 64;
    int z  = blockIdx.z;
    int kb = (INC * z) / GZ;
    int ke = (INC * (z + 1)) / GZ;
    int t  = threadIdx.x;
    int tx = t & 15;
    int ty = t >> 4;
    float acc[4][4] = {};
    float xr[4], wr[8];

#pragma unroll
    for (int l = 0; l < 4; l++) {
        int e = t + l * 128;
        int r = e >> 4, kk = e & 15;
        int gi = i0 + r, gk = kb + kk;
        xr[l] = (gi < N && gk < ke) ? X[(size_t)gi * INC + gk] : 0.f;
    }
#pragma unroll
    for (int l = 0; l < 8; l++) {
        int e = t + l * 128;
        int c = e >> 4, kk = e & 15;
        int gk = kb + kk;
        wr[l] = (gk < ke) ? W[(size_t)(c0 + c) * INC + gk] : 0.f;
    }

    for (int kt = kb; kt < ke; kt += 16) {
#pragma unroll
        for (int l = 0; l < 4; l++) { int e = t + l * 128; Xs[e & 15][e >> 4] = xr[l]; }
#pragma unroll
        for (int l = 0; l < 8; l++) { int e = t + l * 128; Ws[e & 15][e >> 4] = wr[l]; }
        __syncthreads();
        int ktn = kt + 16;
        if (ktn < ke) {
#pragma unroll
            for (int l = 0; l < 4; l++) {
                int e = t + l * 128;
                int r = e >> 4, kk = e & 15;
                int gi = i0 + r, gk = ktn + kk;
                xr[l] = (gi < N && gk < ke) ? X[(size_t)gi * INC + gk] : 0.f;
            }
#pragma unroll
            for (int l = 0; l < 8; l++) {
                int e = t + l * 128;
                int c = e >> 4, kk = e & 15;
                int gk = ktn + kk;
                wr[l] = (gk < ke) ? W[(size_t)(c0 + c) * INC + gk] : 0.f;
            }
        }
#pragma unroll
        for (int kk = 0; kk < 16; kk++) {
            float4 a = *(const float4*)&Xs[kk][4 * ty];
            float4 b = *(const float4*)&Ws[kk][4 * tx];
            acc[0][0] += a.x * b.x; acc[0][1] += a.x * b.y; acc[0][2] += a.x * b.z; acc[0][3] += a.x * b.w;
            acc[1][0] += a.y * b.x; acc[1][1] += a.y * b.y; acc[1][2] += a.y * b.z; acc[1][3] += a.y * b.w;
            acc[2][0] += a.z * b.x; acc[2][1] += a.z * b.y; acc[2][2] += a.z * b.z; acc[2][3] += a.z * b.w;
            acc[3][0] += a.w * b.x; acc[3][1] += a.w * b.y; acc[3][2] += a.w * b.z; acc[3][3] += a.w * b.w;
        }
        __syncthreads();
    }
#pragma unroll
    for (int rr = 0; rr < 4; rr++) {
        int gi = i0 + 4 * ty + rr;
        if (gi < N) {
            float4 v = make_float4(acc[rr][0], acc[rr][1], acc[rr][2], acc[rr][3]);
            *(float4*)&g_Kp[z][(size_t)gi * OC + c0 + 4 * tx] = v;
        }
    }
}

// ---------------- fold GZ partials -> g_K, plus k1,k2 (one warp/row) ---------
__global__ void fold_k1k2(const float* __restrict__ a1, const float* __restrict__ a2) {
    int w = threadIdx.x >> 5;
    int lane = threadIdx.x & 31;
    int i = blockIdx.x * 8 + w;
    if (i >= N) return;
    float d1 = 0.f, d2 = 0.f;
#pragma unroll
    for (int u = 0; u < 4; u++) {
        int c = lane + 32 * u;
        size_t idx = (size_t)i * OC + c;
        float kv = g_Kp[0][idx] + g_Kp[1][idx] + g_Kp[2][idx] + g_Kp[3][idx];
        g_K[idx] = kv;
        d1 += kv * a1[c];
        d2 += kv * a2[c];
    }
#pragma unroll
    for (int off = 16; off; off >>= 1) {
        d1 += __shfl_down_sync(0xffffffffu, d1, off);
        d2 += __shfl_down_sync(0xffffffffu, d2, off);
    }
    if (lane == 0) { g_k1[i] = d1; g_k2[i] = d2; }
}

// ---------------- column partials: t1 = U^T k1, t2 = U^T 1 --------------------
// unroll 4: four independent U loads in flight (MLP) on the DRAM chain.
__global__ void colpart(const float* __restrict__ U) {
    int j  = blockIdx.x * 256 + threadIdx.x;
    int ch = blockIdx.y;
    if (j >= N) return;
    int ib = ch * RC;
    int ie = min(N, ib + RC);
    float a = 0.f, b = 0.f;
#pragma unroll 4
    for (int i = ib; i < ie; i++) {
        float u = U[(size_t)i * N + j];
        a += u * g_k1[i];
        b += u;
    }
    g_part1[ch * N + j] = a;
    g_part2[ch * N + j] = b;
}

// ---------------- s = lmbd * t -------------------------------------------------
__global__ void colreduce(const float* __restrict__ lmbd) {
    int j = blockIdx.x * 256 + threadIdx.x;
    if (j >= N) return;
    float a = 0.f, b = 0.f;
#pragma unroll
    for (int c = 0; c < NCH; c++) {
        a += g_part1[c * N + j];
        b += g_part2[c * N + j];
    }
    float l = lmbd[j];
    g_s1[j] = l * a;
    g_s2[j] = l * b;
}

// ---------------- p = U s1, q = U s2 (float4 both sides) -----------------------
__global__ void pq_kernel(const float* __restrict__ U) {
    __shared__ float r1[256], r2[256];
    int i = blockIdx.x;
    int t = threadIdx.x;
    float a = 0.f, b = 0.f;
    const float4* Ur  = (const float4*)(U + (size_t)i * N);
    const float4* s1v = (const float4*)g_s1;
    const float4* s2v = (const float4*)g_s2;
    for (int j4 = t; j4 < NW4; j4 += 256) {
        float4 u  = Ur[j4];
        float4 s1 = s1v[j4];
        float4 s2 = s2v[j4];
        a += u.x * s1.x + u.y * s1.y + u.z * s1.z + u.w * s1.w;
        b += u.x * s2.x + u.y * s2.y + u.z * s2.z + u.w * s2.w;
    }
    r1[t] = a; r2[t] = b;
    __syncthreads();
    for (int s = 128; s; s >>= 1) {
        if (t < s) { r1[t] += r1[t + s]; r2[t] += r2[t + s]; }
        __syncthreads();
    }
    if (t == 0) { g_p[i] = r1[0]; g_q[i] = r2[0]; }
}

// ---------------- sparse masked-softmax attention (single A pass) --------------
// R15-proven form: block-wide deterministic ballot compaction from smem logits.
__global__ void __launch_bounds__(128) attn_sparse(const int* __restrict__ A,
                                                   float* __restrict__ H) {
    __shared__ float sLog[N];      // masked logits (-1e30 if A_ij = 0)
    __shared__ int   sj[N];        // selected j (ascending)
    __shared__ float sw[N];        // selected weights
    __shared__ float red[128];
    __shared__ int   scnt;
    __shared__ int   wbase[4];

    int i    = blockIdx.x;
    int t    = threadIdx.x;
    int lane = t & 31;
    int wid  = t >> 5;
    float p  = g_p[i];
    float q  = g_q[i];
    const int4* Ap = (const int4*)(A + (size_t)i * N);

    // ---- single A pass: masked logits into smem + per-thread max ------------
    float mloc = -1e30f;
#pragma unroll
    for (int l = 0; l < 6; l++) {
        int i4 = t + 128 * l;
        if (i4 < NW4) {
            int4 av = Ap[i4];
            int j = 4 * i4;
            float x0 = av.x ? fabsf(p + q * __ldg(&g_k2[j]))     : -1e30f;
            float x1 = av.y ? fabsf(p + q * __ldg(&g_k2[j + 1])) : -1e30f;
            float x2 = av.z ? fabsf(p + q * __ldg(&g_k2[j + 2])) : -1e30f;
            float x3 = av.w ? fabsf(p + q * __ldg(&g_k2[j + 3])) : -1e30f;
            sLog[j] = x0; sLog[j + 1] = x1; sLog[j + 2] = x2; sLog[j + 3] = x3;
            mloc = fmaxf(fmaxf(x0, x1), fmaxf(fmaxf(x2, x3), mloc));
        }
    }
    red[t] = mloc;
    __syncthreads();
    for (int s = 64; s; s >>= 1) {
        if (t < s) red[t] = fmaxf(red[t], red[t + s]);
        __syncthreads();
    }
    float m = red[0];
    if (t == 0) scnt = 0;
    __syncthreads();
    float thr = m - XTHR;

    // ---- deterministic compaction of j with logit > m - 25 (from smem) ------
    for (int jb = 0; jb < NPAD; jb += 128) {
        int j = jb + t;
        bool pred = (j < N) && (sLog[j] > thr);
        unsigned bal = __ballot_sync(0xffffffffu, pred);
        int pos  = __popc(bal & ((1u << lane) - 1u));
        if (lane == 0) wbase[wid] = __popc(bal);
        __syncthreads();
        if (t == 0) {
            int b0 = scnt;
#pragma unroll
            for (int w = 0; w < 4; w++) { int tmp = wbase[w]; wbase[w] = b0; b0 += tmp; }
            scnt = b0;
        }
        __syncthreads();
        if (pred) sj[wbase[wid] + pos] = j;
        __syncthreads();
    }
    int cnt = scnt;

    // ---- weights + denominator (tree reduce, deterministic) -----------------
    float ls = 0.f;
    for (int e = t; e < cnt; e += 128) {
        float w = __expf(sLog[sj[e]] - m);
        sw[e] = w;
        ls += w;
    }
    red[t] = ls;
    __syncthreads();
    for (int s = 64; s; s >>= 1) {
        if (t < s) red[t] += red[t + s];
        __syncthreads();
    }
    float l = red[0];
    float inv = (l > 0.f) ? 1.f / l : 0.f;

    // ---- numerator: thread t = output column t, gather selected K rows ------
    float a0 = 0.f, a1 = 0.f, a2 = 0.f, a3 = 0.f;
    int e = 0;
    for (; e + 4 <= cnt; e += 4) {
        a0 += sw[e + 0] * __ldg(&g_K[(size_t)sj[e + 0] * OC + t]);
        a1 += sw[e + 1] * __ldg(&g_K[(size_t)sj[e + 1] * OC + t]);
        a2 += sw[e + 2] * __ldg(&g_K[(size_t)sj[e + 2] * OC + t]);
        a3 += sw[e + 3] * __ldg(&g_K[(size_t)sj[e + 3] * OC + t]);
    }
    for (; e < cnt; e++)
        a0 += sw[e] * __ldg(&g_K[(size_t)sj[e] * OC + t]);
    float acc = (a0 + a1) + (a2 + a3);
    H[(size_t)i * OC + t] = acc * inv;
}

// ---------------- launch --------------------------------------------------------
extern "C" void kernel_launch(void* const* d_in, const int* in_sizes, int n_in,
                              void* d_out, int out_size) {
    (void)in_sizes; (void)n_in; (void)out_size;
    const float* X    = (const float*)d_in[0];
    const int*   A    = (const int*)d_in[1];
    const float* U    = (const float*)d_in[2];
    const float* W    = (const float*)d_in[3];
    const float* a1   = (const float*)d_in[4];
    const float* a2   = (const float*)d_in[5];
    const float* lmbd = (const float*)d_in[6];
    float* H = (float*)d_out;

    gemm_k     <<<dim3(2, (N + 31) / 32, GZ), 128>>>(X, W);
    fold_k1k2  <<<(N + 7) / 8, 256>>>(a1, a2);
    colpart    <<<dim3((N + 255) / 256, NCH), 256>>>(U);
    colreduce  <<<(N + 255) / 256, 256>>>(lmbd);
    pq_kernel  <<<N, 256>>>(U);
    attn_sparse<<<N, 128>>>(A, H);
}